// round 1
// baseline (speedup 1.0000x reference)
#include <cuda_runtime.h>
#include <math.h>

#define BB    16
#define TT    64
#define IND   256
#define HH    512
#define NN    256
#define WWD   64
#define RR    4
#define OUTD  256
#define ITFD  471

// interface vector offsets
#define O_RK 0
#define O_RS 256
#define O_WK 260
#define O_WS 324
#define O_ER 325
#define O_WV 389
#define O_FG 453
#define O_AG 457
#define O_WG 458
#define O_MO 459
#define EPSF 1e-6f

// -------------------- persistent state (device globals) --------------------
__device__ float g_h[2][BB * HH];
__device__ float g_c[BB * HH];
__device__ float g_M[BB * NN * WWD];
__device__ float g_usage[BB * NN];
__device__ float g_link[BB * NN * NN];
__device__ float g_prec[2][BB * NN];
__device__ float g_wr[BB * RR * NN];
__device__ float g_ww[BB * NN];
__device__ float g_rw[BB * RR * WWD];
__device__ float g_itf[BB * ITFD];
__device__ float g_hall[TT * BB * HH];
__device__ float g_rwall[TT * BB * RR * WWD];
__device__ float g_WintT[ITFD * HH];

// -------------------- helpers --------------------
__device__ __forceinline__ float sigf(float x) { return 1.f / (1.f + expf(-x)); }
__device__ __forceinline__ float softplusf(float x) {
    return fmaxf(x, 0.f) + log1pf(expf(-fabsf(x)));
}
__device__ __forceinline__ float oneplusf(float x) { return 1.f + softplusf(x); }

__device__ __forceinline__ float blk_max256(float v, float* red, int tid) {
    red[tid] = v; __syncthreads();
    for (int s = 128; s > 0; s >>= 1) {
        if (tid < s) red[tid] = fmaxf(red[tid], red[tid + s]);
        __syncthreads();
    }
    float r = red[0]; __syncthreads();
    return r;
}
__device__ __forceinline__ float blk_sum256(float v, float* red, int tid) {
    red[tid] = v; __syncthreads();
    for (int s = 128; s > 0; s >>= 1) {
        if (tid < s) red[tid] = red[tid] + red[tid + s];
        __syncthreads();
    }
    float r = red[0]; __syncthreads();
    return r;
}

// -------------------- K0: transpose W_int --------------------
__global__ void k_transpose(const float* __restrict__ Wint) {
    int idx = blockIdx.x * 256 + threadIdx.x;
    if (idx < ITFD * HH) {
        int c = idx / HH;
        int k = idx - c * HH;
        g_WintT[idx] = Wint[k * ITFD + c];
    }
}

// -------------------- K1: fused LSTM (gates + cell) --------------------
// grid 128, block 256. Block handles 4 j values; tid = jj*64 + kc*16 + b.
__global__ void k_lstm(const float* __restrict__ x,
                       const float* __restrict__ Wih,
                       const float* __restrict__ Whh,
                       const float* __restrict__ bih,
                       const float* __restrict__ bhh,
                       int t, int hp) {
    int tid = threadIdx.x;
    int jj = tid >> 6;
    int kc = (tid >> 4) & 3;
    int b  = tid & 15;
    int j  = blockIdx.x * 4 + jj;

    const float* hprev = g_h[hp];
    const float* src;
    if (kc < 2) src = x + ((size_t)t * BB + b) * IND + kc * 128;
    else        src = g_rw + b * (RR * WWD) + (kc - 2) * 128;

    float ai = 0.f, af = 0.f, ag = 0.f, ao = 0.f;
    {
        const float* wi = Wih + ((size_t)(0 * HH + j)) * 512 + kc * 128;
        const float* wf = Wih + ((size_t)(1 * HH + j)) * 512 + kc * 128;
        const float* wg = Wih + ((size_t)(2 * HH + j)) * 512 + kc * 128;
        const float* wo = Wih + ((size_t)(3 * HH + j)) * 512 + kc * 128;
        #pragma unroll 8
        for (int kk = 0; kk < 128; kk++) {
            float v = src[kk];
            ai += v * wi[kk]; af += v * wf[kk]; ag += v * wg[kk]; ao += v * wo[kk];
        }
    }
    {
        const float* hs = hprev + b * HH + kc * 128;
        const float* wi = Whh + ((size_t)(0 * HH + j)) * 512 + kc * 128;
        const float* wf = Whh + ((size_t)(1 * HH + j)) * 512 + kc * 128;
        const float* wg = Whh + ((size_t)(2 * HH + j)) * 512 + kc * 128;
        const float* wo = Whh + ((size_t)(3 * HH + j)) * 512 + kc * 128;
        #pragma unroll 8
        for (int kk = 0; kk < 128; kk++) {
            float v = hs[kk];
            ai += v * wi[kk]; af += v * wf[kk]; ag += v * wg[kk]; ao += v * wo[kk];
        }
    }
    __shared__ float sred[4][256];
    sred[0][tid] = ai; sred[1][tid] = af; sred[2][tid] = ag; sred[3][tid] = ao;
    __syncthreads();
    if (kc == 0) {
        int base = jj * 64 + b;
        float si = sred[0][base] + sred[0][base + 16] + sred[0][base + 32] + sred[0][base + 48];
        float sf = sred[1][base] + sred[1][base + 16] + sred[1][base + 32] + sred[1][base + 48];
        float sg = sred[2][base] + sred[2][base + 16] + sred[2][base + 32] + sred[2][base + 48];
        float so = sred[3][base] + sred[3][base + 16] + sred[3][base + 32] + sred[3][base + 48];
        float gi = si + bih[0 * HH + j] + bhh[0 * HH + j];
        float gf = sf + bih[1 * HH + j] + bhh[1 * HH + j];
        float gg = sg + bih[2 * HH + j] + bhh[2 * HH + j];
        float go = so + bih[3 * HH + j] + bhh[3 * HH + j];
        float cold = g_c[b * HH + j];
        float cn = sigf(gf) * cold + sigf(gi) * tanhf(gg);
        float hn = sigf(go) * tanhf(cn);
        g_c[b * HH + j] = cn;
        g_h[hp ^ 1][b * HH + j] = hn;
        g_hall[((size_t)t * BB + b) * HH + j] = hn;
    }
}

// -------------------- K2: interface GEMM --------------------
// grid 59, block 256. 8 cols per block; tid = cc*32 + kc*16 + b.
__global__ void k_itf(const float* __restrict__ bint, int hc) {
    int tid = threadIdx.x;
    int cc = tid >> 5;
    int lane = tid & 31;
    int kc = lane >> 4;
    int b = lane & 15;
    int c = blockIdx.x * 8 + cc;
    float acc = 0.f;
    if (c < ITFD) {
        const float* w = g_WintT + (size_t)c * HH + kc * 256;
        const float* h = g_h[hc] + b * HH + kc * 256;
        #pragma unroll 8
        for (int kk = 0; kk < 256; kk++) acc += h[kk] * w[kk];
    }
    acc += __shfl_xor_sync(0xffffffffu, acc, 16);
    if (c < ITFD && kc == 0) g_itf[b * ITFD + c] = acc + bint[c];
}

// -------------------- K3: per-batch write addressing --------------------
// grid 16, block 256.
__global__ void k_write(int par) {
    int b = blockIdx.x;
    int tid = threadIdx.x;
    __shared__ float uval[NN];
    __shared__ int   uidx[NN];
    __shared__ float ps[NN];
    __shared__ float cw[NN];
    __shared__ float allocv[NN];
    __shared__ float red[NN];
    __shared__ float karr[WWD];
    __shared__ float sc_knorm, sc_beta;

    const float* itf = g_itf + (size_t)b * ITFD;

    float fg0 = sigf(itf[O_FG + 0]);
    float fg1 = sigf(itf[O_FG + 1]);
    float fg2 = sigf(itf[O_FG + 2]);
    float fg3 = sigf(itf[O_FG + 3]);
    float ag  = sigf(itf[O_AG]);
    float wg  = sigf(itf[O_WG]);

    // usage update
    int n = tid;
    float psi = 1.f;
    psi *= (1.f - fg0 * g_wr[(b * RR + 0) * NN + n]);
    psi *= (1.f - fg1 * g_wr[(b * RR + 1) * NN + n]);
    psi *= (1.f - fg2 * g_wr[(b * RR + 2) * NN + n]);
    psi *= (1.f - fg3 * g_wr[(b * RR + 3) * NN + n]);
    float u = g_usage[b * NN + n];
    float wagg = g_ww[b * NN + n];  // NW=1 -> 1-(1-ww)=ww
    float un = (u + wagg - u * wagg) * psi;
    uval[tid] = un; uidx[tid] = tid;
    g_usage[b * NN + n] = un;

    if (tid < WWD) karr[tid] = itf[O_WK + tid];
    __syncthreads();
    if (tid == 0) {
        float ss = 0.f;
        for (int w = 0; w < WWD; w++) ss += karr[w] * karr[w];
        sc_knorm = sqrtf(ss) + EPSF;
        sc_beta  = oneplusf(itf[O_WS]);
    }
    __syncthreads();

    // content write scores
    float dot = 0.f, ss = 0.f;
    const float* Mrow = g_M + ((size_t)(b * NN) + n) * WWD;
    #pragma unroll 8
    for (int w = 0; w < WWD; w++) {
        float m = Mrow[w];
        dot += m * karr[w];
        ss += m * m;
    }
    float sim = (dot / sc_knorm) / (sqrtf(ss) + EPSF);
    float sco = sc_beta * sim;
    float mx = blk_max256(sco, red, tid);
    float e = expf(sco - mx);
    float sm = blk_sum256(e, red, tid);
    cw[tid] = e / sm;
    __syncthreads();

    // stable bitonic sort ascending on (uval, uidx)
    for (int k2 = 2; k2 <= NN; k2 <<= 1) {
        for (int jmp = k2 >> 1; jmp > 0; jmp >>= 1) {
            __syncthreads();
            int ixj = tid ^ jmp;
            if (ixj > tid) {
                float v0 = uval[tid], v1 = uval[ixj];
                int i0 = uidx[tid], i1 = uidx[ixj];
                bool up = ((tid & k2) == 0);
                bool gt = (v0 > v1) || (v0 == v1 && i0 > i1);
                if (gt == up) {
                    uval[tid] = v1; uval[ixj] = v0;
                    uidx[tid] = i1; uidx[ixj] = i0;
                }
            }
        }
    }
    __syncthreads();

    // inclusive product scan of sorted usage
    ps[tid] = uval[tid];
    __syncthreads();
    for (int off = 1; off < NN; off <<= 1) {
        float v = (tid >= off) ? ps[tid - off] : 1.f;
        __syncthreads();
        ps[tid] *= v;
        __syncthreads();
    }
    float excl = (tid > 0) ? ps[tid - 1] : 1.f;
    float a = (1.f - uval[tid]) * excl;
    allocv[uidx[tid]] = a;
    __syncthreads();

    float wwn = wg * (ag * allocv[tid] + (1.f - ag) * cw[tid]);
    g_ww[b * NN + tid] = wwn;
    float wsum = blk_sum256(wwn, red, tid);
    float pold = g_prec[par][b * NN + tid];
    g_prec[par ^ 1][b * NN + tid] = (1.f - wsum) * pold + wwn;
}

// -------------------- K4: link + memory update --------------------
// grid 320, block 256. blocks [0,256): link; [256,320): M.
__global__ void k_mem(int par) {
    int blk = blockIdx.x;
    int tid = threadIdx.x;
    if (blk < 256) {
        int b = blk >> 4;
        int it = blk & 15;
        int i = it * 16 + (tid >> 4);
        int j0 = tid & 15;
        float wwi = g_ww[b * NN + i];
        const float* pre = g_prec[par] + b * NN;
        const float* wwp = g_ww + b * NN;
        float* lrow = g_link + ((size_t)(b * NN) + i) * NN;
        #pragma unroll 4
        for (int jj = 0; jj < 16; jj++) {
            int j = j0 + jj * 16;
            float v;
            if (i == j) v = 0.f;
            else v = (1.f - wwi - wwp[j]) * lrow[j] + wwi * pre[j];
            lrow[j] = v;
        }
    } else {
        int m = blk - 256;
        int row = m * 64 + (tid >> 2);  // global (b*N + n)
        int w0 = (tid & 3) * 16;
        int b = row >> 8;
        const float* itf = g_itf + (size_t)b * ITFD;
        float wwn = g_ww[row];
        float* Mp = g_M + (size_t)row * WWD + w0;
        #pragma unroll 4
        for (int q = 0; q < 16; q++) {
            int w = w0 + q;
            float er = sigf(itf[O_ER + w]);
            float vv = sigf(itf[O_WV + w]);
            Mp[q] = Mp[q] * (1.f - wwn * er) + wwn * vv;
        }
    }
}

// -------------------- K5: per-batch read addressing --------------------
// grid 16, block 256.
__global__ void k_read(int t) {
    int b = blockIdx.x;
    int tid = threadIdx.x;
    __shared__ float kn[RR][WWD];
    __shared__ float wr_s[RR][NN];
    __shared__ float fwd[RR][NN];
    __shared__ float bwd[RR][NN];
    __shared__ float cr[RR][NN];
    __shared__ float red[NN];
    __shared__ float betas[RR], knorm[RR], mbv[RR], mfv[RR], mcv[RR];

    const float* itf = g_itf + (size_t)b * ITFD;

    for (int idx = tid; idx < RR * NN; idx += 256)
        wr_s[idx >> 8][idx & 255] = g_wr[b * RR * NN + idx];
    {
        int r = tid >> 6, w = tid & 63;
        kn[r][w] = itf[O_RK + r * WWD + w];
    }
    __syncthreads();
    if (tid < RR) {
        float ss = 0.f;
        for (int w = 0; w < WWD; w++) ss += kn[tid][w] * kn[tid][w];
        knorm[tid] = sqrtf(ss) + EPSF;
        betas[tid] = oneplusf(itf[O_RS + tid]);
        float m0 = itf[O_MO + tid * 3 + 0];
        float m1 = itf[O_MO + tid * 3 + 1];
        float m2 = itf[O_MO + tid * 3 + 2];
        float mx = fmaxf(m0, fmaxf(m1, m2));
        float e0 = expf(m0 - mx), e1 = expf(m1 - mx), e2 = expf(m2 - mx);
        float s = e0 + e1 + e2;
        mbv[tid] = e0 / s; mfv[tid] = e1 / s; mcv[tid] = e2 / s;
    }
    __syncthreads();

    // content read scores
    int n = tid;
    float d0 = 0.f, d1 = 0.f, d2 = 0.f, d3 = 0.f, ss = 0.f;
    const float* Mrow = g_M + ((size_t)(b * NN) + n) * WWD;
    #pragma unroll 8
    for (int w = 0; w < WWD; w++) {
        float m = Mrow[w];
        ss += m * m;
        d0 += m * kn[0][w]; d1 += m * kn[1][w]; d2 += m * kn[2][w]; d3 += m * kn[3][w];
    }
    float inv = 1.f / (sqrtf(ss) + EPSF);
    float scv[4];
    scv[0] = betas[0] * (d0 / knorm[0]) * inv;
    scv[1] = betas[1] * (d1 / knorm[1]) * inv;
    scv[2] = betas[2] * (d2 / knorm[2]) * inv;
    scv[3] = betas[3] * (d3 / knorm[3]) * inv;
    for (int r = 0; r < RR; r++) {
        float mx = blk_max256(scv[r], red, tid);
        float e = expf(scv[r] - mx);
        float sm = blk_sum256(e, red, tid);
        cr[r][tid] = e / sm;
    }
    __syncthreads();

    // bwd[r][i] = sum_j link[b][j][i] * wr_prev[r][j]  (coalesced on i)
    {
        float a0 = 0.f, a1 = 0.f, a2 = 0.f, a3 = 0.f;
        for (int j = 0; j < NN; j++) {
            float lv = g_link[((size_t)(b * NN) + j) * NN + tid];
            a0 += lv * wr_s[0][j]; a1 += lv * wr_s[1][j];
            a2 += lv * wr_s[2][j]; a3 += lv * wr_s[3][j];
        }
        bwd[0][tid] = a0; bwd[1][tid] = a1; bwd[2][tid] = a2; bwd[3][tid] = a3;
    }
    // fwd[r][i] = sum_j link[b][i][j] * wr_prev[r][j]  (warp per row)
    {
        int warp = tid >> 5, lane = tid & 31;
        for (int rr = 0; rr < 32; rr++) {
            int i = warp * 32 + rr;
            const float* lrow = g_link + ((size_t)(b * NN) + i) * NN;
            float a0 = 0.f, a1 = 0.f, a2 = 0.f, a3 = 0.f;
            for (int j = lane; j < NN; j += 32) {
                float lv = lrow[j];
                a0 += lv * wr_s[0][j]; a1 += lv * wr_s[1][j];
                a2 += lv * wr_s[2][j]; a3 += lv * wr_s[3][j];
            }
            #pragma unroll
            for (int off = 16; off > 0; off >>= 1) {
                a0 += __shfl_down_sync(0xffffffffu, a0, off);
                a1 += __shfl_down_sync(0xffffffffu, a1, off);
                a2 += __shfl_down_sync(0xffffffffu, a2, off);
                a3 += __shfl_down_sync(0xffffffffu, a3, off);
            }
            if (lane == 0) { fwd[0][i] = a0; fwd[1][i] = a1; fwd[2][i] = a2; fwd[3][i] = a3; }
        }
    }
    __syncthreads();

    float wrn[4];
    #pragma unroll
    for (int r = 0; r < RR; r++)
        wrn[r] = mbv[r] * bwd[r][tid] + mfv[r] * fwd[r][tid] + mcv[r] * cr[r][tid];
    __syncthreads();
    #pragma unroll
    for (int r = 0; r < RR; r++) {
        wr_s[r][tid] = wrn[r];
        g_wr[(b * RR + r) * NN + tid] = wrn[r];
    }
    __syncthreads();

    // read_words[r][w] = sum_n wr[r][n] * M[b][n][w]
    {
        int r = tid >> 6, w = tid & 63;
        float acc = 0.f;
        for (int n2 = 0; n2 < NN; n2++)
            acc += wr_s[r][n2] * g_M[((size_t)(b * NN) + n2) * WWD + w];
        g_rw[(b * RR + r) * WWD + w] = acc;
        g_rwall[((size_t)t * BB + b) * (RR * WWD) + r * WWD + w] = acc;
    }
}

// -------------------- K6: batched output GEMM --------------------
// C[tb, o] = sum_k pre[tb,k] * Wout[o,k] + bout[o], pre = [h | rw], K=768
__global__ void k_out(const float* __restrict__ Wout,
                      const float* __restrict__ bout,
                      float* __restrict__ out) {
    __shared__ float As[32][33];
    __shared__ float Bs[32][33];
    int tx = threadIdx.x & 15, ty = threadIdx.x >> 4;
    int tb0 = blockIdx.x * 32, o0 = blockIdx.y * 32;
    float acc00 = 0.f, acc01 = 0.f, acc10 = 0.f, acc11 = 0.f;
    for (int kt = 0; kt < 768; kt += 32) {
        for (int l = threadIdx.x; l < 1024; l += 256) {
            int mi = l >> 5, ki = l & 31;
            int k = kt + ki;
            int tb = tb0 + mi;
            float av = (k < 512) ? g_hall[(size_t)tb * HH + k]
                                 : g_rwall[(size_t)tb * (RR * WWD) + (k - 512)];
            As[mi][ki] = av;
            Bs[mi][ki] = Wout[(size_t)(o0 + mi) * 768 + k];
        }
        __syncthreads();
        #pragma unroll 8
        for (int ki = 0; ki < 32; ki++) {
            float a0 = As[ty * 2][ki], a1 = As[ty * 2 + 1][ki];
            float b0 = Bs[tx * 2][ki], b1 = Bs[tx * 2 + 1][ki];
            acc00 += a0 * b0; acc01 += a0 * b1;
            acc10 += a1 * b0; acc11 += a1 * b1;
        }
        __syncthreads();
    }
    int tb = tb0 + ty * 2, o = o0 + tx * 2;
    float bo0 = bout[o], bo1 = bout[o + 1];
    out[(size_t)tb * OUTD + o] = acc00 + bo0;
    out[(size_t)tb * OUTD + o + 1] = acc01 + bo1;
    out[(size_t)(tb + 1) * OUTD + o] = acc10 + bo0;
    out[(size_t)(tb + 1) * OUTD + o + 1] = acc11 + bo1;
}

// -------------------- host launch --------------------
extern "C" void kernel_launch(void* const* d_in, const int* in_sizes, int n_in,
                              void* d_out, int out_size) {
    const float* x    = (const float*)d_in[0];
    const float* Wih  = (const float*)d_in[1];
    const float* Whh  = (const float*)d_in[2];
    const float* bih  = (const float*)d_in[3];
    const float* bhh  = (const float*)d_in[4];
    const float* Wint = (const float*)d_in[5];
    const float* bint = (const float*)d_in[6];
    const float* Wout = (const float*)d_in[7];
    const float* bout = (const float*)d_in[8];
    float* out = (float*)d_out;

    void* p;
    cudaGetSymbolAddress(&p, g_h);     cudaMemsetAsync(p, 0, sizeof(float) * 2 * BB * HH);
    cudaGetSymbolAddress(&p, g_c);     cudaMemsetAsync(p, 0, sizeof(float) * BB * HH);
    cudaGetSymbolAddress(&p, g_M);     cudaMemsetAsync(p, 0, sizeof(float) * BB * NN * WWD);
    cudaGetSymbolAddress(&p, g_usage); cudaMemsetAsync(p, 0, sizeof(float) * BB * NN);
    cudaGetSymbolAddress(&p, g_link);  cudaMemsetAsync(p, 0, sizeof(float) * BB * NN * NN);
    cudaGetSymbolAddress(&p, g_prec);  cudaMemsetAsync(p, 0, sizeof(float) * 2 * BB * NN);
    cudaGetSymbolAddress(&p, g_wr);    cudaMemsetAsync(p, 0, sizeof(float) * BB * RR * NN);
    cudaGetSymbolAddress(&p, g_ww);    cudaMemsetAsync(p, 0, sizeof(float) * BB * NN);
    cudaGetSymbolAddress(&p, g_rw);    cudaMemsetAsync(p, 0, sizeof(float) * BB * RR * WWD);

    k_transpose<<<(ITFD * HH + 255) / 256, 256>>>(Wint);

    for (int t = 0; t < TT; t++) {
        int par = t & 1;
        k_lstm<<<128, 256>>>(x, Wih, Whh, bih, bhh, t, par);
        k_itf<<<59, 256>>>(bint, par ^ 1);
        k_write<<<16, 256>>>(par);
        k_mem<<<320, 256>>>(par);
        k_read<<<16, 256>>>(t);
    }
    k_out<<<dim3(32, 8), 256>>>(Wout, bout, out);
}